// round 16
// baseline (speedup 1.0000x reference)
#include <cuda_runtime.h>
#include <cstddef>

#define NEGF (-10000.0f)
constexpr int S_LEN = 1024;
constexpr int NLAB  = 49;
constexpr int L     = 51;   // start = 49, end = 50

__device__ int d_perm[4096];   // rank -> batch index (B <= 4096)

__device__ __forceinline__ unsigned long long pk2(float a, float b) {
    unsigned long long r;
    asm("mov.b64 %0, {%1, %2};" : "=l"(r) : "f"(a), "f"(b));
    return r;
}
__device__ __forceinline__ void upk2(unsigned long long v, float& a, float& b) {
    asm("mov.b64 {%0, %1}, %2;" : "=f"(a), "=f"(b) : "l"(v));
}

// one-row (or one-col) 25-pack dot over slots 0..49 of a 56-float shared vec.
#define DOT25(QP, EARR, OUT)                                                      \
    do {                                                                          \
        unsigned long long c0 = 0ull, c1 = 0ull;                                  \
        _Pragma("unroll")                                                         \
        for (int mm = 0; mm < 12; mm++) {                                         \
            ulonglong2 qv = (QP)[mm];                                             \
            asm("fma.rn.f32x2 %0, %1, %2, %0;" : "+l"(c0) : "l"(qv.x), "l"(EARR[2*mm]));   \
            asm("fma.rn.f32x2 %0, %1, %2, %0;" : "+l"(c1) : "l"(qv.y), "l"(EARR[2*mm+1])); \
        }                                                                         \
        {                                                                         \
            ulonglong2 qv = (QP)[12];                                             \
            asm("fma.rn.f32x2 %0, %1, %2, %0;" : "+l"(c0) : "l"(qv.x), "l"(EARR[24]));     \
        }                                                                         \
        unsigned long long sall;                                                  \
        asm("add.rn.f32x2 %0, %1, %2;" : "=l"(sall) : "l"(c0), "l"(c1));          \
        float z0, z1;                                                             \
        upk2(sall, z0, z1);                                                       \
        OUT = z0 + z1;                                                            \
    } while (0)

#define FBAR() asm volatile("bar.sync 1, 64;" ::: "memory")
#define BBAR() asm volatile("bar.sync 2, 64;" ::: "memory")

// ---- rank kernel: d_perm[rank(len_i)] = i (stable) ----
__global__ void rank_kernel(const int* __restrict__ lens, int B)
{
    int i = blockIdx.x * blockDim.x + threadIdx.x;
    if (i >= B) return;
    int li = lens[i];
    int r = 0;
    for (int j = 0; j < B; j++) {
        int lj = __ldg(lens + j);
        r += (lj < li) || (lj == li && j < i);
    }
    d_perm[r] = i;
}

// 128 threads: warps 0,1 = forward rows {0-25, 26-50}; warps 2,3 = backward
// cols {0-25, 26-50}. One sequence pair per CTA (length-balanced, serial).
__global__ __launch_bounds__(128) void crf_fwd_kernel(
    const float* __restrict__ logits,   // [B, S, NL]
    const float* __restrict__ trans,    // [L, L]
    const int*   __restrict__ labels,   // [B, S]
    const int*   __restrict__ lens,     // [B]
    float*       __restrict__ out,      // [B]
    int Btot)
{
    __shared__ __align__(16) float ash[2][56];   // alpha (slots 49..55 stay ~0)
    __shared__ __align__(16) float wsh[2][56];   // bwd w = v*beta (padded)
    __shared__ __align__(16) float bsh[56];      // beta_m output
    __shared__ float norm_sh;
    __shared__ int   eaccB_sh;
    __shared__ float red[128];

    const int c    = blockIdx.x;
    const int tid  = threadIdx.x;
    const int wid  = tid >> 5;
    const int lane = tid & 31;
    const int dir  = wid >> 1;          // 0 = fwd, 1 = bwd
    const int half = wid & 1;           // 0: base 0, 1: base 26

    const int  idx  = half * 26 + lane;                 // row (fwd) / col (bwd)
    const bool owns = lane <= (half ? 24 : 25);         // idx <= 50
    const bool hasV = owns && idx <= 48;                // has a logit stream
    const int  sidx = owns ? idx : 0;                   // safe index for loads

    // ---- sequence-invariant eT table: one row (fwd) or one col (bwd) ----
    unsigned long long eT[25];
    if (dir == 0) {
        const float* r = trans + sidx * L;
        #pragma unroll
        for (int p = 0; p < 25; p++) {
            float a = owns ? __expf(r[2 * p])     : 0.0f;
            float b = owns ? __expf(r[2 * p + 1]) : 0.0f;
            eT[p] = pk2(a, b);
        }
    } else {
        #pragma unroll
        for (int p = 0; p < 25; p++) {
            float a = owns ? __expf(__ldg(trans + (2 * p) * L + sidx))     : 0.0f;
            float b = owns ? __expf(__ldg(trans + (2 * p + 1) * L + sidx)) : 0.0f;
            eT[p] = pk2(a, b);
        }
    }
    const float beta0 = (dir == 1 && owns) ? __expf(__ldg(trans + 50 * L + sidx)) : 0.0f;

    for (int i = tid; i < 56; i += 128) {
        ash[0][i] = 0.0f; ash[1][i] = 0.0f;
        wsh[0][i] = 0.0f; wsh[1][i] = 0.0f;
        bsh[i] = 0.0f;
    }
    __syncthreads();

    const int npairs = (Btot + 1) >> 1;
    (void)npairs;

    #pragma unroll 1
    for (int s = 0; s < 2; s++) {
        const int pidx = s == 0 ? c : (Btot - 1 - c);
        if (s == 1 && pidx <= c) break;
        const int b   = d_perm[pidx];
        const int len = lens[b];
        const int m   = (len + 1) >> 1;
        const float* lp = logits + (size_t)b * S_LEN * NLAB;

        int Eacc = 0;

        if (dir == 0) {
            // ================= FORWARD =================
            if (hasV)
                ash[1][idx] = __expf(__ldg(lp + idx) + __ldg(trans + idx * L + 49));

            float rl[8];
            #pragma unroll
            for (int i = 0; i < 8; i++)
                rl[i] = hasV ? __ldg(lp + (size_t)(1 + i) * NLAB + idx) : NEGF;
            float v = __expf(rl[0]);
            FBAR();

            for (int tb = 1; tb < m; tb += 8) {
                #pragma unroll
                for (int i = 0; i < 8; i++) {
                    const int t = tb + i;
                    if (t >= m) break;
                    const int par = t & 1;
                    const ulonglong2* qp = reinterpret_cast<const ulonglong2*>(ash[par]);

                    float q0 = ash[par][0];
                    int be = __float_as_int(q0) >> 23;       // q0 > 0
                    Eacc += be - 127;
                    float sc = __int_as_float((254 - be) << 23);
                    float u  = v * sc;

                    const int ni = (i + 1) & 7;
                    float vN = __expf(rl[ni]);
                    if (hasV && t + 8 < m)
                        rl[i] = __ldg(lp + (size_t)(t + 8) * NLAB + idx);

                    float S;
                    DOT25(qp, eT, S);

                    if (owns) ash[par ^ 1][idx] = S * u;
                    FBAR();
                    v = vN;
                }
            }
        } else {
            // ================= BACKWARD =================
            float beta = beta0;
            if (wid == 2 && lane == 0) { wsh[0][0] = 1.0f; wsh[1][0] = 1.0f; }
            BBAR();

            float rl[8];
            #pragma unroll
            for (int i = 0; i < 8; i++) {
                int tr = len - 1 - i >= 0 ? len - 1 - i : 0;
                rl[i] = hasV ? __ldg(lp + (size_t)tr * NLAB + idx) : NEGF;
            }
            float v = __expf(rl[0]);

            for (int tb = len - 1; tb >= m; tb -= 8) {
                #pragma unroll
                for (int i = 0; i < 8; i++) {
                    const int t = tb - i;
                    if (t < m) break;
                    const int par = t & 1;

                    float w0 = wsh[par ^ 1][0];              // prev step (barriered)
                    int be = __float_as_int(w0) >> 23;       // w0 > 0
                    Eacc += be - 127;
                    float sc = __int_as_float((254 - be) << 23);

                    if (owns) wsh[par][idx] = v * beta * sc;
                    BBAR();

                    const int ni = (i + 1) & 7;
                    float vN = __expf(rl[ni]);
                    if (hasV && t - 8 >= m)
                        rl[i] = __ldg(lp + (size_t)(t - 8) * NLAB + idx);

                    const ulonglong2* qp = reinterpret_cast<const ulonglong2*>(wsh[par]);
                    float Snew;
                    DOT25(qp, eT, Snew);
                    beta = Snew;
                    v = vN;
                }
            }
            if (owns) bsh[idx] = beta;
            if (wid == 2 && lane == 0) eaccB_sh = Eacc;
        }
        __syncthreads();

        // ---- Z = alpha_m . beta_m ; norm = log Z + (EF+EB) ln2 (warp 0) ----
        if (wid == 0) {
            const int fpar = m & 1;
            float z = ash[fpar][lane] * bsh[lane];
            if (lane < 17) z += ash[fpar][lane + 32] * bsh[lane + 32];
            #pragma unroll
            for (int o = 16; o; o >>= 1) z += __shfl_down_sync(0xffffffffu, z, o);
            if (lane == 0)
                norm_sh = (float)((double)__logf(z) +
                                  (double)(Eacc + eaccB_sh) * 0.6931471805599453);
        }

        // ---- gold = unary + binary (128-thread gather) ----
        const int* labp = labels + (size_t)b * S_LEN;
        float acc = 0.0f;
        #pragma unroll 4
        for (int t = tid; t < len; t += 128) {
            int lab = labp[t];
            acc += __ldg(lp + (size_t)t * NLAB + lab);
            int prev = t ? labp[t - 1] : (L - 2);
            acc += __ldg(trans + lab * L + prev);
        }
        if (tid == 0) acc += __ldg(trans + 50 * L + labp[len - 1]);
        red[tid] = acc;
        __syncthreads();

        if (wid == 0) {
            float vv = (red[lane] + red[lane + 32]) + (red[lane + 64] + red[lane + 96]);
            #pragma unroll
            for (int o = 16; o; o >>= 1) vv += __shfl_down_sync(0xffffffffu, vv, o);
            if (lane == 0) out[b] = vv - norm_sh;
        }
        __syncthreads();   // protect shared reuse by next sequence
    }
}

extern "C" void kernel_launch(void* const* d_in, const int* in_sizes, int n_in,
                              void* d_out, int out_size)
{
    const float* logits = (const float*)d_in[0];
    const float* trans  = (const float*)d_in[1];
    const int*   labels = (const int*)d_in[2];
    const int*   lens   = (const int*)d_in[3];
    const int B = in_sizes[3];

    rank_kernel<<<(B + 255) / 256, 256>>>(lens, B);
    crf_fwd_kernel<<<(B + 1) / 2, 128>>>(logits, trans, labels, lens,
                                         (float*)d_out, B);
}

// round 17
// speedup vs baseline: 1.2504x; 1.2504x over previous
#include <cuda_runtime.h>
#include <cstddef>

#define NEGF (-10000.0f)
constexpr int S_LEN = 1024;
constexpr int NLAB  = 49;
constexpr int L     = 51;   // start = 49, end = 50

__device__ int d_perm[4096];   // rank -> batch index (B <= 4096)

__device__ __forceinline__ unsigned long long pk2(float a, float b) {
    unsigned long long r;
    asm("mov.b64 %0, {%1, %2};" : "=l"(r) : "f"(a), "f"(b));
    return r;
}
__device__ __forceinline__ void upk2(unsigned long long v, float& a, float& b) {
    asm("mov.b64 {%0, %1}, %2;" : "=f"(a), "=f"(b) : "l"(v));
}

// Converged-warp exchange fence: compiler-only. The loop body is branch-free
// (predicated lane guards), so the warp stays converged; same-warp SMEM ops
// drain in issue order through the LSU.
#define WEXCH() asm volatile("" ::: "memory")

// 25-pack dot over index 0..49 of a 56-float shared vector; loads stay inside
// (ptxas schedules/CSEs them). 2 chains — the measured-fastest structure.
#define DOTQ(QP, EARR, OUT)                                                       \
    do {                                                                          \
        unsigned long long c0 = 0ull, c1 = 0ull;                                  \
        _Pragma("unroll")                                                         \
        for (int mm = 0; mm < 12; mm++) {                                         \
            ulonglong2 qv = (QP)[mm];                                             \
            asm("fma.rn.f32x2 %0, %1, %2, %0;" : "+l"(c0) : "l"(qv.x), "l"(EARR[2*mm]));   \
            asm("fma.rn.f32x2 %0, %1, %2, %0;" : "+l"(c1) : "l"(qv.y), "l"(EARR[2*mm+1])); \
        }                                                                         \
        {                                                                         \
            ulonglong2 qv = (QP)[12];                                             \
            asm("fma.rn.f32x2 %0, %1, %2, %0;" : "+l"(c0) : "l"(qv.x), "l"(EARR[24]));     \
        }                                                                         \
        unsigned long long sall;                                                  \
        asm("add.rn.f32x2 %0, %1, %2;" : "=l"(sall) : "l"(c0), "l"(c1));          \
        float z0, z1;                                                             \
        upk2(sall, z0, z1);                                                       \
        OUT = z0 + z1;                                                            \
    } while (0)

// ---- rank kernel: d_perm[rank(len_i)] = i (stable) ----
__global__ void rank_kernel(const int* __restrict__ lens, int B)
{
    int i = blockIdx.x * blockDim.x + threadIdx.x;
    if (i >= B) return;
    int li = lens[i];
    int r = 0;
    for (int j = 0; j < B; j++) {
        int lj = __ldg(lens + j);
        r += (lj < li) || (lj == li && j < i);
    }
    d_perm[r] = i;
}

__global__ __launch_bounds__(64) void crf_fwd_kernel(
    const float* __restrict__ logits,   // [B, S, NL]
    const float* __restrict__ trans,    // [L, L]
    const int*   __restrict__ labels,   // [B, S]
    const int*   __restrict__ lens,     // [B]
    float*       __restrict__ out,      // [B]
    int Btot)
{
    __shared__ __align__(16) float ash[2][56];   // forward alpha (slots 49..55 = 0)
    __shared__ __align__(16) float wsh[2][56];   // backward w = v*beta (padded)
    __shared__ __align__(16) float bsh[56];      // beta_m output
    __shared__ float norm_sh;
    __shared__ int   eaccB_sh;
    __shared__ float red[64];

    const int c    = blockIdx.x;
    const int tid  = threadIdx.x;
    const int wid  = tid >> 5;
    const int lane = tid & 31;

    const bool hasHi = lane < 17;       // second state/column = lane+32 (32..48)
    const int  hi    = lane + 32;

    // ---- sequence-invariant setup: exp(T) tables per warp role ----
    unsigned long long eLo[25], eHi[25];
    float r50lo = 0.0f, r50hi = 0.0f;   // bwd only: r[j] = exp(T[end=50, j])
    if (wid == 0) {
        const float* rlo = trans + lane * L;
        const float* rhi = trans + (hasHi ? hi : 0) * L;
        #pragma unroll
        for (int p = 0; p < 25; p++) {
            eLo[p] = pk2(__expf(rlo[2 * p]), __expf(rlo[2 * p + 1]));
            float d = 0.0f, e = 0.0f;
            if (hasHi) { d = __expf(rhi[2 * p]); e = __expf(rhi[2 * p + 1]); }
            eHi[p] = pk2(d, e);
        }
    } else {
        #pragma unroll
        for (int p = 0; p < 25; p++) {
            eLo[p] = pk2(__expf(__ldg(trans + (2 * p) * L + lane)),
                         __expf(__ldg(trans + (2 * p + 1) * L + lane)));
            float d = 0.0f, e = 0.0f;
            if (hasHi) {
                d = __expf(__ldg(trans + (2 * p) * L + hi));
                e = __expf(__ldg(trans + (2 * p + 1) * L + hi));
            }
            eHi[p] = pk2(d, e);
        }
        r50lo = __expf(__ldg(trans + 50 * L + lane));
        r50hi = hasHi ? __expf(__ldg(trans + 50 * L + hi)) : 0.0f;
    }

    for (int i = tid; i < 56; i += 64) { ash[0][i] = 0.0f; ash[1][i] = 0.0f;
                                         wsh[0][i] = 0.0f; wsh[1][i] = 0.0f;
                                         bsh[i] = 0.0f; }
    __syncthreads();

    // ---- two length-balanced sequences per CTA ----
    #pragma unroll 1
    for (int s = 0; s < 2; s++) {
        const int pidx = s == 0 ? c : (Btot - 1 - c);
        if (s == 1 && pidx <= c) break;
        const int b   = d_perm[pidx];
        const int len = lens[b];
        const int m   = (len + 1) >> 1;
        const float* lp = logits + (size_t)b * S_LEN * NLAB;

        int Eacc = 0;

        if (wid == 0) {
            // ================= FORWARD (rows of E) =================
            ash[1][lane] = __expf(__ldg(lp + lane) + __ldg(trans + lane * L + 49));
            if (hasHi)
                ash[1][hi] = __expf(__ldg(lp + hi) + __ldg(trans + hi * L + 49));

            float rl[8], rh[8];
            #pragma unroll
            for (int i = 0; i < 8; i++) {
                rl[i] = __ldg(lp + (size_t)(1 + i) * NLAB + lane);
                rh[i] = hasHi ? __ldg(lp + (size_t)(1 + i) * NLAB + hi) : NEGF;
            }
            float vlo = __expf(rl[0]);
            float vhi = hasHi ? __expf(rh[0]) : 0.0f;
            __syncwarp();

            for (int tb = 1; tb < m; tb += 8) {
                #pragma unroll
                for (int i = 0; i < 8; i++) {
                    const int t = tb + i;
                    if (t >= m) break;
                    const int par = t & 1;
                    const ulonglong2* qp = reinterpret_cast<const ulonglong2*>(ash[par]);

                    float q0 = ash[par][0];
                    int be = __float_as_int(q0) >> 23;       // q0 > 0
                    Eacc += be - 127;
                    float sc  = __int_as_float((254 - be) << 23);
                    float ulo = vlo * sc;
                    float uhi = vhi * sc;

                    const int ni = (i + 1) & 7;
                    float vloN = __expf(rl[ni]);
                    float vhiN = hasHi ? __expf(rh[ni]) : 0.0f;
                    if (t + 8 < m) {
                        rl[i] = __ldg(lp + (size_t)(t + 8) * NLAB + lane);
                        if (hasHi) rh[i] = __ldg(lp + (size_t)(t + 8) * NLAB + hi);
                    }

                    float Slo, Shi;
                    DOTQ(qp, eLo, Slo);
                    DOTQ(qp, eHi, Shi);

                    ash[par ^ 1][lane] = Slo * ulo;
                    if (hasHi) ash[par ^ 1][hi] = Shi * uhi;
                    WEXCH();
                    vlo = vloN; vhi = vhiN;
                }
            }
            __syncwarp();
        } else {
            // ================= BACKWARD (columns of E) =================
            float blo = r50lo;
            float bhi = r50hi;
            if (lane == 0) { wsh[0][0] = 1.0f; wsh[1][0] = 1.0f; }  // seed sc = 1
            __syncwarp();

            float rl[8], rh[8];
            #pragma unroll
            for (int i = 0; i < 8; i++) {
                int tr = len - 1 - i >= 0 ? len - 1 - i : 0;
                rl[i] = __ldg(lp + (size_t)tr * NLAB + lane);
                rh[i] = hasHi ? __ldg(lp + (size_t)tr * NLAB + hi) : NEGF;
            }
            float vlo = __expf(rl[0]);
            float vhi = hasHi ? __expf(rh[0]) : 0.0f;
            __syncwarp();

            for (int tb = len - 1; tb >= m; tb -= 8) {
                #pragma unroll
                for (int i = 0; i < 8; i++) {
                    const int t = tb - i;
                    if (t < m) break;
                    const int par = t & 1;

                    float w0 = wsh[par ^ 1][0];              // stored by previous step
                    int be = __float_as_int(w0) >> 23;       // w0 > 0
                    Eacc += be - 127;
                    float sc = __int_as_float((254 - be) << 23);

                    wsh[par][lane] = vlo * blo * sc;
                    if (hasHi) wsh[par][hi] = vhi * bhi * sc;
                    WEXCH();

                    const int ni = (i + 1) & 7;
                    float vloN = __expf(rl[ni]);
                    float vhiN = hasHi ? __expf(rh[ni]) : 0.0f;
                    if (t - 8 >= m) {
                        rl[i] = __ldg(lp + (size_t)(t - 8) * NLAB + lane);
                        if (hasHi) rh[i] = __ldg(lp + (size_t)(t - 8) * NLAB + hi);
                    }

                    const ulonglong2* qp = reinterpret_cast<const ulonglong2*>(wsh[par]);
                    float Sl, Sh;
                    DOTQ(qp, eLo, Sl);
                    DOTQ(qp, eHi, Sh);
                    blo = Sl;
                    bhi = hasHi ? Sh : 0.0f;
                    vlo = vloN; vhi = vhiN;
                }
            }
            __syncwarp();
            bsh[lane] = blo;
            if (hasHi) bsh[hi] = bhi;
            if (lane == 0) eaccB_sh = Eacc;
        }
        __syncthreads();

        // ---- Z = alpha_m . beta_m ; norm = log Z + (EF+EB) ln2  (warp 0) ----
        if (wid == 0) {
            const int fpar = m & 1;
            float z = ash[fpar][lane] * bsh[lane];
            if (hasHi) z += ash[fpar][hi] * bsh[hi];
            #pragma unroll
            for (int o = 16; o; o >>= 1) z += __shfl_down_sync(0xffffffffu, z, o);
            if (lane == 0)
                norm_sh = (float)((double)__logf(z) +
                                  (double)(Eacc + eaccB_sh) * 0.6931471805599453);
        }

        // ---- gold = unary + binary (64-thread gather) ----
        const int* labp = labels + (size_t)b * S_LEN;
        float acc = 0.0f;
        #pragma unroll 4
        for (int t = tid; t < len; t += 64) {
            int lab = labp[t];
            acc += __ldg(lp + (size_t)t * NLAB + lab);
            int prev = t ? labp[t - 1] : (L - 2);
            acc += __ldg(trans + lab * L + prev);
        }
        if (tid == 0) acc += __ldg(trans + 50 * L + labp[len - 1]);
        red[tid] = acc;
        __syncthreads();

        if (tid < 32) {
            float v = red[tid] + red[tid + 32];
            #pragma unroll
            for (int o = 16; o; o >>= 1) v += __shfl_down_sync(0xffffffffu, v, o);
            if (tid == 0) out[b] = v - norm_sh;
        }
        __syncthreads();   // protect shared reuse by next sequence
    }
}

extern "C" void kernel_launch(void* const* d_in, const int* in_sizes, int n_in,
                              void* d_out, int out_size)
{
    const float* logits = (const float*)d_in[0];
    const float* trans  = (const float*)d_in[1];
    const int*   labels = (const int*)d_in[2];
    const int*   lens   = (const int*)d_in[3];
    const int B = in_sizes[3];

    rank_kernel<<<(B + 255) / 256, 256>>>(lens, B);
    crf_fwd_kernel<<<(B + 1) / 2, 64>>>(logits, trans, labels, lens,
                                        (float*)d_out, B);
}